// round 12
// baseline (speedup 1.0000x reference)
#include <cuda_runtime.h>
#include <cuda_fp16.h>
#include <cstdint>

#define NN 50000
#define NE 800000
#define D  128
#define NBLK 98                  // ceil(50000/512) scan blocks
#define GBLK 782                 // ceil(50000/64) gemm blocks

// ---- scratch (no allocations allowed) ----
__device__ int      g_deg[NN];
__device__ int      g_rowptr[NN + 1];
__device__ int      g_srcd[NE];      // staged src
__device__ int      g_dstd[NE];      // staged dst
__device__ int      g_pos[NE];       // staged within-dst slot
__device__ int2     g_edge[NE];      // CSR: {src, dis[src] bits}
__device__ float    g_dis[NN];
__device__ __half2  g_h2[NN * 64];   // GEMM output, fp16 (128 cols = 64 half2)
__device__ float    g_x1[NN * D];    // layer-1 activation (fp32)
__device__ int      g_part[NBLK];
__device__ int      g_pdone;
__device__ int      g_is64;
__device__ unsigned g_wf[2][16384];  // fragment-ordered tf32 weights

__device__ __forceinline__ unsigned to_tf32(float f) {
    unsigned r;
    asm("cvt.rna.tf32.f32 %0, %1;" : "=r"(r) : "f"(f));
    return r;
}

// init: zero deg, reset scan flag, dtype-detect, build fragment-ordered tf32 W1/W2.
__global__ void k_init(const int* __restrict__ ei32,
                       const float* __restrict__ W1,
                       const float* __restrict__ W2) {
    int i = blockIdx.x * blockDim.x + threadIdx.x;
    if (i < NN) g_deg[i] = 0;
    if (i == 0) g_pdone = 0;
    if (i < 32768) {
        int l  = (i >= 16384) ? 1 : 0;
        int j  = i & 16383;
        int r  = j & 1;
        int ln = (j >> 1) & 31;
        int nt = (j >> 6) & 15;
        int kt = j >> 10;
        int k  = kt * 8 + (ln & 3) + r * 4;
        int n  = nt * 8 + (ln >> 2);
        const float* W = l ? W2 : W1;
        g_wf[l][j] = to_tf32(W[k * 128 + n]);
    }
    if (blockIdx.x == 0 && threadIdx.x < 32) {
        int lane = threadIdx.x;
        int acc = 0;
        for (int jj = 0; jj < 8; jj++) acc |= ei32[1 + 2 * (lane + 32 * jj)];
        unsigned b = __ballot_sync(0xFFFFFFFFu, acc != 0);
        if (lane == 0) g_is64 = (b == 0) ? 1 : 0;
    }
}

// decode + degree-count + slot assignment (single atomic pass over edges)
__global__ void k_prep(const void* __restrict__ eiv) {
    int e = blockIdx.x * blockDim.x + threadIdx.x;
    if (e >= NE) return;
    int s, d;
    if (g_is64) {
        const long long* ei = (const long long*)eiv;
        s = (int)ei[e];
        d = (int)ei[NE + e];
    } else {
        const int* ei = (const int*)eiv;
        s = ei[e];
        d = ei[NE + e];
    }
    if ((unsigned)s >= NN) s = 0;
    if ((unsigned)d >= NN) d = 0;
    int pos = atomicAdd(&g_deg[d], 1);
    g_srcd[e] = s;
    g_dstd[e] = d;
    g_pos[e]  = pos;
}

// fused dis + exclusive scan (98 blocks <= 148 SMs -> co-resident, spin safe)
__global__ void k_scan_all() {
    __shared__ int sh[512];
    __shared__ int s_prefix;
    int t = threadIdx.x, b = blockIdx.x;
    int i = b * 512 + t;

    int dg = 0;
    if (i < NN) {
        dg = g_deg[i];
        g_dis[i] = rsqrtf((float)(dg + 1));
    }
    sh[t] = dg;
    __syncthreads();
    for (int o = 1; o < 512; o <<= 1) {
        int a = (t >= o) ? sh[t - o] : 0;
        __syncthreads();
        sh[t] += a;
        __syncthreads();
    }
    int incl = sh[t];

    if (t == 511) {
        g_part[b] = incl;
        __threadfence();
        atomicAdd(&g_pdone, 1);
    }
    if (t == 0) {
        volatile int* p = &g_pdone;
        while (*p < NBLK) {}
    }
    __syncthreads();

    if (t < 32) {
        int s = 0;
        for (int j = t; j < b; j += 32) s += __ldcg(&g_part[j]);
#pragma unroll
        for (int o = 16; o > 0; o >>= 1) s += __shfl_down_sync(0xFFFFFFFFu, s, o);
        if (t == 0) s_prefix = s;
    }
    __syncthreads();

    if (i < NN) g_rowptr[i] = s_prefix + incl - dg;   // exclusive
    if (i == 0) g_rowptr[NN] = NE;
}

// atomic-free CSR fill: pure staged-read -> scatter-write
__global__ void k_fill() {
    int e = blockIdx.x * blockDim.x + threadIdx.x;
    if (e >= NE) return;
    int s   = g_srcd[e];
    int d   = g_dstd[e];
    int pos = g_pos[e];
    g_edge[g_rowptr[d] + pos] = make_int2(s, __float_as_int(g_dis[s]));
}

// ---------------------------------------------------------------------------
// tf32 tensor-core GEMM: g_h2[NN,128](fp16) = x[NN,128] @ W[128,128]
// ---------------------------------------------------------------------------
__global__ void k_gemm(const float* __restrict__ x_ext, int use_x1, int wsel) {
    const float* x = use_x1 ? g_x1 : x_ext;
    __shared__ float As[64 * 128];

    int t    = threadIdx.x;
    int base = blockIdx.x * 64;

    const float4* x4 = (const float4*)x;
    for (int i = t; i < 64 * 32; i += 256) {
        int r = i >> 5, c4 = i & 31;
        int gr = base + r;
        float4 v = make_float4(0.f, 0.f, 0.f, 0.f);
        if (gr < NN) v = x4[gr * 32 + c4];
        ((float4*)As)[r * 32 + (c4 ^ (r & 7))] = v;
    }
    __syncthreads();

    int wid  = t >> 5;
    int lane = t & 31;
    int gid  = lane >> 2;
    int tig  = lane & 3;
    int wr   = wid & 3;
    int wc   = wid >> 2;

    const uint2* wf = (const uint2*)g_wf[wsel];

    float acc[8][4];
#pragma unroll
    for (int n = 0; n < 8; n++)
#pragma unroll
        for (int j = 0; j < 4; j++) acc[n][j] = 0.f;

    int rA = wr * 16 + gid;
    int sw = gid << 2;

#pragma unroll
    for (int kt = 0; kt < 16; kt++) {
        int k0 = kt * 8;
        unsigned a0 = to_tf32(As[rA * 128 + ((k0 + tig) ^ sw)]);
        unsigned a1 = to_tf32(As[(rA + 8) * 128 + ((k0 + tig) ^ sw)]);
        unsigned a2 = to_tf32(As[rA * 128 + ((k0 + tig + 4) ^ sw)]);
        unsigned a3 = to_tf32(As[(rA + 8) * 128 + ((k0 + tig + 4) ^ sw)]);
#pragma unroll
        for (int nt = 0; nt < 8; nt++) {
            uint2 b = wf[(kt * 16 + wc * 8 + nt) * 32 + lane];
            asm volatile(
                "mma.sync.aligned.m16n8k8.row.col.f32.tf32.tf32.f32 "
                "{%0,%1,%2,%3}, {%4,%5,%6,%7}, {%8,%9}, {%0,%1,%2,%3};"
                : "+f"(acc[nt][0]), "+f"(acc[nt][1]),
                  "+f"(acc[nt][2]), "+f"(acc[nt][3])
                : "r"(a0), "r"(a1), "r"(a2), "r"(a3), "r"(b.x), "r"(b.y));
        }
    }

    int row0 = base + wr * 16 + gid;
#pragma unroll
    for (int nt = 0; nt < 8; nt++) {
        int c2i = wc * 32 + nt * 4 + tig;
        if (row0 < NN)
            g_h2[row0 * 64 + c2i] = __floats2half2_rn(acc[nt][0], acc[nt][1]);
        if (row0 + 8 < NN)
            g_h2[(row0 + 8) * 64 + c2i] = __floats2half2_rn(acc[nt][2], acc[nt][3]);
    }
}

// 8-col fp16 fma: u = 16B = 8 halves; acc = 8 floats
__device__ __forceinline__ void agg_fma8(float* a, float c, uint4 u) {
    float2 f0 = __half22float2(*(const __half2*)&u.x);
    float2 f1 = __half22float2(*(const __half2*)&u.y);
    float2 f2 = __half22float2(*(const __half2*)&u.z);
    float2 f3 = __half22float2(*(const __half2*)&u.w);
    a[0] = fmaf(c, f0.x, a[0]);
    a[1] = fmaf(c, f0.y, a[1]);
    a[2] = fmaf(c, f1.x, a[2]);
    a[3] = fmaf(c, f1.y, a[3]);
    a[4] = fmaf(c, f2.x, a[4]);
    a[5] = fmaf(c, f2.y, a[5]);
    a[6] = fmaf(c, f3.x, a[6]);
    a[7] = fmaf(c, f3.y, a[7]);
}

// Aggregation: one warp per node, HALF-WARP per edge.
// lanes 0-15 -> edge e, lanes 16-31 -> edge e+1; each lane loads uint4 (16B,
// 8 cols). Unroll x4 pairs => 8 edges & 4 loads in flight per lane.
// Combine half-warps via shfl_xor(16) at the end.
__global__ void k_agg(const float* __restrict__ bias, float* __restrict__ out_ext,
                      int layer) {
    int node = blockIdx.x * (blockDim.x >> 5) + (threadIdx.x >> 5);
    if (node >= NN) return;
    int lane = threadIdx.x & 31;
    int half = lane >> 4;       // 0: even edges, 1: odd edges
    int hl   = lane & 15;       // uint4 column index (8 cols each)

    int beg = g_rowptr[node];
    int end = g_rowptr[node + 1];

    const uint4* h16 = (const uint4*)g_h2;   // 16 uint4 per row

    float A0[8], A1[8], A2[8], A3[8];
#pragma unroll
    for (int j = 0; j < 8; j++) { A0[j] = 0.f; A1[j] = 0.f; A2[j] = 0.f; A3[j] = 0.f; }

    int e = beg;
    for (; e + 7 < end; e += 8) {
        int2 p0 = g_edge[e     + half];
        int2 p1 = g_edge[e + 2 + half];
        int2 p2 = g_edge[e + 4 + half];
        int2 p3 = g_edge[e + 6 + half];
        uint4 u0 = h16[p0.x * 16 + hl];
        uint4 u1 = h16[p1.x * 16 + hl];
        uint4 u2 = h16[p2.x * 16 + hl];
        uint4 u3 = h16[p3.x * 16 + hl];
        agg_fma8(A0, __int_as_float(p0.y), u0);
        agg_fma8(A1, __int_as_float(p1.y), u1);
        agg_fma8(A2, __int_as_float(p2.y), u2);
        agg_fma8(A3, __int_as_float(p3.y), u3);
    }
    for (; e + 1 < end; e += 2) {
        int2 p0 = g_edge[e + half];
        uint4 u0 = h16[p0.x * 16 + hl];
        agg_fma8(A0, __int_as_float(p0.y), u0);
    }
    if (e < end && half == 0) {
        int2 p0 = g_edge[e];
        uint4 u0 = h16[p0.x * 16 + hl];
        agg_fma8(A1, __int_as_float(p0.y), u0);
    }

    float acc[8];
#pragma unroll
    for (int j = 0; j < 8; j++) {
        acc[j] = A0[j] + A1[j] + A2[j] + A3[j];
        acc[j] += __shfl_xor_sync(0xFFFFFFFFu, acc[j], 16);
    }

    // self term + bias (cols [hl*8, hl*8+8))
    float dn = g_dis[node];
    float sn = dn * dn;
    uint4 uh = h16[node * 16 + hl];
    float2 s0 = __half22float2(*(const __half2*)&uh.x);
    float2 s1 = __half22float2(*(const __half2*)&uh.y);
    float2 s2 = __half22float2(*(const __half2*)&uh.z);
    float2 s3 = __half22float2(*(const __half2*)&uh.w);
    const float4* b4 = (const float4*)bias;
    float4 ba = b4[hl * 2];
    float4 bb = b4[hl * 2 + 1];

    float r[8];
    r[0] = dn * acc[0] + sn * s0.x + ba.x;
    r[1] = dn * acc[1] + sn * s0.y + ba.y;
    r[2] = dn * acc[2] + sn * s1.x + ba.z;
    r[3] = dn * acc[3] + sn * s1.y + ba.w;
    r[4] = dn * acc[4] + sn * s2.x + bb.x;
    r[5] = dn * acc[5] + sn * s2.y + bb.y;
    r[6] = dn * acc[6] + sn * s3.x + bb.z;
    r[7] = dn * acc[7] + sn * s3.y + bb.w;

    if (layer == 0) {
#pragma unroll
        for (int j = 0; j < 8; j++) r[j] = fmaxf(r[j], 0.f);
    }

    // both halves hold identical r; half 0 writes cols [hl*8,+4), half 1 [hl*8+4,+4)
    float4 w = half ? make_float4(r[4], r[5], r[6], r[7])
                    : make_float4(r[0], r[1], r[2], r[3]);
    float* outp = (layer == 0) ? g_x1 : out_ext;
    ((float4*)outp)[node * 32 + hl * 2 + half] = w;
}

extern "C" void kernel_launch(void* const* d_in, const int* in_sizes, int n_in,
                              void* d_out, int out_size) {
    const void*  ei  = d_in[0];
    const float* emb = (const float*)d_in[1];
    const float* W1  = (const float*)d_in[2];
    const float* b1  = (const float*)d_in[3];
    const float* W2  = (const float*)d_in[4];
    const float* b2  = (const float*)d_in[5];
    float* out = (float*)d_out;

    (void)in_sizes; (void)n_in; (void)out_size;

    k_init<<<196, 256>>>((const int*)ei, W1, W2);   // zero+detect+wfrag
    k_prep<<<(NE + 255) / 256, 256>>>(ei);          // decode+count+slot (1 atomic pass)
    k_scan_all<<<NBLK, 512>>>();                    // dis + exclusive scan
    k_fill<<<(NE + 255) / 256, 256>>>();            // atomic-free scatter

    k_gemm<<<GBLK, 256>>>(emb, 0, 0);               // layer-1 GEMM (tf32 -> fp16 h)
    k_agg<<<(NN + 7) / 8, 256>>>(b1, out, 0);       // -> g_x1 (relu, fp32)

    k_gemm<<<GBLK, 256>>>(nullptr, 1, 1);           // layer-2 GEMM
    k_agg<<<(NN + 7) / 8, 256>>>(b2, out, 1);       // -> d_out
}

// round 14
// speedup vs baseline: 1.0836x; 1.0836x over previous
#include <cuda_runtime.h>
#include <cuda_fp16.h>
#include <cstdint>

#define NN 50000
#define NE 800000
#define D  128
#define NBLK 98                  // ceil(50000/512) scan blocks
#define GBLK 782                 // ceil(50000/64) gemm blocks

// ---- scratch (no allocations allowed) ----
__device__ int      g_deg[NN];
__device__ int      g_rowptr[NN + 1];
__device__ int      g_srcd[NE];      // staged src
__device__ int      g_dstd[NE];      // staged dst
__device__ int      g_pos[NE];       // staged within-dst slot
__device__ int      g_csrc[NE];      // CSR: src per slot (dis folded into h)
__device__ float    g_dis[NN];
__device__ __half2  g_h2[NN * 64];   // GEMM output, fp16, pre-scaled by dis[row]
__device__ float    g_x1[NN * D];    // layer-1 activation (fp32)
__device__ int      g_part[NBLK];
__device__ int      g_pdone;
__device__ int      g_is64;
__device__ unsigned g_wf[2][16384];  // fragment-ordered tf32 weights

__device__ __forceinline__ unsigned to_tf32(float f) {
    unsigned r;
    asm("cvt.rna.tf32.f32 %0, %1;" : "=r"(r) : "f"(f));
    return r;
}

// init: zero deg, reset scan flag, dtype-detect, build fragment-ordered tf32 W1/W2.
__global__ void k_init(const int* __restrict__ ei32,
                       const float* __restrict__ W1,
                       const float* __restrict__ W2) {
    int i = blockIdx.x * blockDim.x + threadIdx.x;
    if (i < NN) g_deg[i] = 0;
    if (i == 0) g_pdone = 0;
    if (i < 32768) {
        int l  = (i >= 16384) ? 1 : 0;
        int j  = i & 16383;
        int r  = j & 1;
        int ln = (j >> 1) & 31;
        int nt = (j >> 6) & 15;
        int kt = j >> 10;
        int k  = kt * 8 + (ln & 3) + r * 4;
        int n  = nt * 8 + (ln >> 2);
        const float* W = l ? W2 : W1;
        g_wf[l][j] = to_tf32(W[k * 128 + n]);
    }
    if (blockIdx.x == 0 && threadIdx.x < 32) {
        int lane = threadIdx.x;
        int acc = 0;
        for (int jj = 0; jj < 8; jj++) acc |= ei32[1 + 2 * (lane + 32 * jj)];
        unsigned b = __ballot_sync(0xFFFFFFFFu, acc != 0);
        if (lane == 0) g_is64 = (b == 0) ? 1 : 0;
    }
}

// decode + degree-count + slot assignment (single atomic pass over edges)
__global__ void k_prep(const void* __restrict__ eiv) {
    int e = blockIdx.x * blockDim.x + threadIdx.x;
    if (e >= NE) return;
    int s, d;
    if (g_is64) {
        const long long* ei = (const long long*)eiv;
        s = (int)ei[e];
        d = (int)ei[NE + e];
    } else {
        const int* ei = (const int*)eiv;
        s = ei[e];
        d = ei[NE + e];
    }
    if ((unsigned)s >= NN) s = 0;
    if ((unsigned)d >= NN) d = 0;
    int pos = atomicAdd(&g_deg[d], 1);
    g_srcd[e] = s;
    g_dstd[e] = d;
    g_pos[e]  = pos;
}

// fused dis + exclusive scan (98 blocks <= 148 SMs -> co-resident, spin safe)
__global__ void k_scan_all() {
    __shared__ int sh[512];
    __shared__ int s_prefix;
    int t = threadIdx.x, b = blockIdx.x;
    int i = b * 512 + t;

    int dg = 0;
    if (i < NN) {
        dg = g_deg[i];
        g_dis[i] = rsqrtf((float)(dg + 1));
    }
    sh[t] = dg;
    __syncthreads();
    for (int o = 1; o < 512; o <<= 1) {
        int a = (t >= o) ? sh[t - o] : 0;
        __syncthreads();
        sh[t] += a;
        __syncthreads();
    }
    int incl = sh[t];

    if (t == 511) {
        g_part[b] = incl;
        __threadfence();
        atomicAdd(&g_pdone, 1);
    }
    if (t == 0) {
        volatile int* p = &g_pdone;
        while (*p < NBLK) {}
    }
    __syncthreads();

    if (t < 32) {
        int s = 0;
        for (int j = t; j < b; j += 32) s += __ldcg(&g_part[j]);
#pragma unroll
        for (int o = 16; o > 0; o >>= 1) s += __shfl_down_sync(0xFFFFFFFFu, s, o);
        if (t == 0) s_prefix = s;
    }
    __syncthreads();

    if (i < NN) g_rowptr[i] = s_prefix + incl - dg;   // exclusive
    if (i == 0) g_rowptr[NN] = NE;
}

// atomic-free CSR fill: staged-read -> 4B scatter-write (src only)
__global__ void k_fill() {
    int e = blockIdx.x * blockDim.x + threadIdx.x;
    if (e >= NE) return;
    int s   = g_srcd[e];
    int d   = g_dstd[e];
    int pos = g_pos[e];
    g_csrc[g_rowptr[d] + pos] = s;
}

// ---------------------------------------------------------------------------
// tf32 tensor-core GEMM: g_h2[row] = dis[row] * (x[row] @ W), fp16 store.
// ---------------------------------------------------------------------------
__global__ void k_gemm(const float* __restrict__ x_ext, int use_x1, int wsel) {
    const float* x = use_x1 ? g_x1 : x_ext;
    __shared__ float As[64 * 128];

    int t    = threadIdx.x;
    int base = blockIdx.x * 64;

    const float4* x4 = (const float4*)x;
    for (int i = t; i < 64 * 32; i += 256) {
        int r = i >> 5, c4 = i & 31;
        int gr = base + r;
        float4 v = make_float4(0.f, 0.f, 0.f, 0.f);
        if (gr < NN) v = x4[gr * 32 + c4];
        ((float4*)As)[r * 32 + (c4 ^ (r & 7))] = v;
    }
    __syncthreads();

    int wid  = t >> 5;
    int lane = t & 31;
    int gid  = lane >> 2;
    int tig  = lane & 3;
    int wr   = wid & 3;
    int wc   = wid >> 2;

    const uint2* wf = (const uint2*)g_wf[wsel];

    float acc[8][4];
#pragma unroll
    for (int n = 0; n < 8; n++)
#pragma unroll
        for (int j = 0; j < 4; j++) acc[n][j] = 0.f;

    int rA = wr * 16 + gid;
    int sw = gid << 2;

#pragma unroll
    for (int kt = 0; kt < 16; kt++) {
        int k0 = kt * 8;
        unsigned a0 = to_tf32(As[rA * 128 + ((k0 + tig) ^ sw)]);
        unsigned a1 = to_tf32(As[(rA + 8) * 128 + ((k0 + tig) ^ sw)]);
        unsigned a2 = to_tf32(As[rA * 128 + ((k0 + tig + 4) ^ sw)]);
        unsigned a3 = to_tf32(As[(rA + 8) * 128 + ((k0 + tig + 4) ^ sw)]);
#pragma unroll
        for (int nt = 0; nt < 8; nt++) {
            uint2 b = wf[(kt * 16 + wc * 8 + nt) * 32 + lane];
            asm volatile(
                "mma.sync.aligned.m16n8k8.row.col.f32.tf32.tf32.f32 "
                "{%0,%1,%2,%3}, {%4,%5,%6,%7}, {%8,%9}, {%0,%1,%2,%3};"
                : "+f"(acc[nt][0]), "+f"(acc[nt][1]),
                  "+f"(acc[nt][2]), "+f"(acc[nt][3])
                : "r"(a0), "r"(a1), "r"(a2), "r"(a3), "r"(b.x), "r"(b.y));
        }
    }

    int row0 = base + wr * 16 + gid;
    float dn0 = (row0 < NN)     ? g_dis[row0]     : 0.f;
    float dn8 = (row0 + 8 < NN) ? g_dis[row0 + 8] : 0.f;
#pragma unroll
    for (int nt = 0; nt < 8; nt++) {
        int c2i = wc * 32 + nt * 4 + tig;
        if (row0 < NN)
            g_h2[row0 * 64 + c2i] =
                __floats2half2_rn(dn0 * acc[nt][0], dn0 * acc[nt][1]);
        if (row0 + 8 < NN)
            g_h2[(row0 + 8) * 64 + c2i] =
                __floats2half2_rn(dn8 * acc[nt][2], dn8 * acc[nt][3]);
    }
}

__device__ __forceinline__ void agg_add(float4& a, uint2 u) {
    float2 lo = __half22float2(*(const __half2*)&u.x);
    float2 hi = __half22float2(*(const __half2*)&u.y);
    a.x += lo.x;
    a.y += lo.y;
    a.z += hi.x;
    a.w += hi.y;
}

// Aggregation (R11 structure, unweighted): one warp per node; lane = 4 cols.
// out[d] = dis[d] * ( sum_e h'[src_e] + h'[d] ) + bias,  h' = dis*h (fp16)
__global__ void k_agg(const float* __restrict__ bias, float* __restrict__ out_ext,
                      int layer) {
    int node = blockIdx.x * (blockDim.x >> 5) + (threadIdx.x >> 5);
    if (node >= NN) return;
    int lane = threadIdx.x & 31;

    int beg = g_rowptr[node];
    int end = g_rowptr[node + 1];

    const uint2* h8 = (const uint2*)g_h2;
    float4 A0 = make_float4(0.f, 0.f, 0.f, 0.f);
    float4 A1 = make_float4(0.f, 0.f, 0.f, 0.f);
    float4 A2 = make_float4(0.f, 0.f, 0.f, 0.f);
    float4 A3 = make_float4(0.f, 0.f, 0.f, 0.f);

    int e = beg;
    for (; e + 3 < end; e += 4) {
        int s0 = g_csrc[e];
        int s1 = g_csrc[e + 1];
        int s2 = g_csrc[e + 2];
        int s3 = g_csrc[e + 3];
        uint2 u0 = h8[s0 * 32 + lane];
        uint2 u1 = h8[s1 * 32 + lane];
        uint2 u2 = h8[s2 * 32 + lane];
        uint2 u3 = h8[s3 * 32 + lane];
        agg_add(A0, u0);
        agg_add(A1, u1);
        agg_add(A2, u2);
        agg_add(A3, u3);
    }
    if (e + 1 < end) {
        int s0 = g_csrc[e];
        int s1 = g_csrc[e + 1];
        uint2 u0 = h8[s0 * 32 + lane];
        uint2 u1 = h8[s1 * 32 + lane];
        agg_add(A0, u0);
        agg_add(A1, u1);
        e += 2;
    }
    if (e < end) {
        int s0 = g_csrc[e];
        uint2 u0 = h8[s0 * 32 + lane];
        agg_add(A0, u0);
    }

    // self term (h' already dis-scaled)
    uint2 uh = h8[node * 32 + lane];
    agg_add(A0, uh);

    A0.x += A1.x + A2.x + A3.x;
    A0.y += A1.y + A2.y + A3.y;
    A0.z += A1.z + A2.z + A3.z;
    A0.w += A1.w + A2.w + A3.w;

    float dn = g_dis[node];
    float4 b = ((const float4*)bias)[lane];

    float4 r;
    r.x = dn * A0.x + b.x;
    r.y = dn * A0.y + b.y;
    r.z = dn * A0.z + b.z;
    r.w = dn * A0.w + b.w;

    if (layer == 0) {
        r.x = fmaxf(r.x, 0.f);
        r.y = fmaxf(r.y, 0.f);
        r.z = fmaxf(r.z, 0.f);
        r.w = fmaxf(r.w, 0.f);
        ((float4*)g_x1)[node * 32 + lane] = r;
    } else {
        ((float4*)out_ext)[node * 32 + lane] = r;
    }
}

extern "C" void kernel_launch(void* const* d_in, const int* in_sizes, int n_in,
                              void* d_out, int out_size) {
    const void*  ei  = d_in[0];
    const float* emb = (const float*)d_in[1];
    const float* W1  = (const float*)d_in[2];
    const float* b1  = (const float*)d_in[3];
    const float* W2  = (const float*)d_in[4];
    const float* b2  = (const float*)d_in[5];
    float* out = (float*)d_out;

    (void)in_sizes; (void)n_in; (void)out_size;

    k_init<<<196, 256>>>((const int*)ei, W1, W2);   // zero+detect+wfrag
    k_prep<<<(NE + 255) / 256, 256>>>(ei);          // decode+count+slot (1 atomic pass)
    k_scan_all<<<NBLK, 512>>>();                    // dis + exclusive scan
    k_fill<<<(NE + 255) / 256, 256>>>();            // atomic-free 4B scatter

    k_gemm<<<GBLK, 256>>>(emb, 0, 0);               // layer-1 GEMM (tf32 -> dis*h fp16)
    k_agg<<<(NN + 7) / 8, 256>>>(b1, out, 0);       // -> g_x1 (relu, fp32)

    k_gemm<<<GBLK, 256>>>(nullptr, 1, 1);           // layer-2 GEMM
    k_agg<<<(NN + 7) / 8, 256>>>(b2, out, 1);       // -> d_out
}

// round 15
// speedup vs baseline: 1.2272x; 1.1325x over previous
#include <cuda_runtime.h>
#include <cuda_fp16.h>
#include <cstdint>

#define NN 50000
#define NE 800000
#define D  128
#define NBLK 98                  // ceil(50000/512) scan blocks
#define GBLK 782                 // ceil(50000/64) gemm blocks

// ---- scratch (no allocations allowed) ----
__device__ int      g_deg[NN];
__device__ int      g_rowptr[NN + 1];
__device__ int      g_srcd[NE];      // staged src
__device__ int      g_dstd[NE];      // staged dst
__device__ int      g_pos[NE];       // staged within-dst slot
__device__ int      g_csrc[NE];      // CSR: src per slot (dis folded into h)
__device__ float    g_dis[NN];
__device__ __half2  g_h2[NN * 64];   // GEMM output, fp16, pre-scaled by dis[row]
__device__ float    g_x1[NN * D];    // layer-1 activation (fp32)
__device__ int      g_part[NBLK];
__device__ int      g_pdone;
__device__ int      g_is64;
__device__ unsigned g_wf[2][16384];  // fragment-ordered tf32 weights

__device__ __forceinline__ unsigned to_tf32(float f) {
    unsigned r;
    asm("cvt.rna.tf32.f32 %0, %1;" : "=r"(r) : "f"(f));
    return r;
}

// init: zero deg, reset scan flag, dtype-detect, build fragment-ordered tf32 W1/W2.
__global__ void k_init(const int* __restrict__ ei32,
                       const float* __restrict__ W1,
                       const float* __restrict__ W2) {
    int i = blockIdx.x * blockDim.x + threadIdx.x;
    if (i < NN) g_deg[i] = 0;
    if (i == 0) g_pdone = 0;
    if (i < 32768) {
        int l  = (i >= 16384) ? 1 : 0;
        int j  = i & 16383;
        int r  = j & 1;
        int ln = (j >> 1) & 31;
        int nt = (j >> 6) & 15;
        int kt = j >> 10;
        int k  = kt * 8 + (ln & 3) + r * 4;
        int n  = nt * 8 + (ln >> 2);
        const float* W = l ? W2 : W1;
        g_wf[l][j] = to_tf32(W[k * 128 + n]);
    }
    if (blockIdx.x == 0 && threadIdx.x < 32) {
        int lane = threadIdx.x;
        int acc = 0;
        for (int jj = 0; jj < 8; jj++) acc |= ei32[1 + 2 * (lane + 32 * jj)];
        unsigned b = __ballot_sync(0xFFFFFFFFu, acc != 0);
        if (lane == 0) g_is64 = (b == 0) ? 1 : 0;
    }
}

// decode + degree-count + slot assignment (single atomic pass over edges)
__global__ void k_prep(const void* __restrict__ eiv) {
    int e = blockIdx.x * blockDim.x + threadIdx.x;
    if (e >= NE) return;
    int s, d;
    if (g_is64) {
        const long long* ei = (const long long*)eiv;
        s = (int)ei[e];
        d = (int)ei[NE + e];
    } else {
        const int* ei = (const int*)eiv;
        s = ei[e];
        d = ei[NE + e];
    }
    if ((unsigned)s >= NN) s = 0;
    if ((unsigned)d >= NN) d = 0;
    int pos = atomicAdd(&g_deg[d], 1);
    g_srcd[e] = s;
    g_dstd[e] = d;
    g_pos[e]  = pos;
}

// fused dis + exclusive scan (98 blocks <= 148 SMs -> co-resident, spin safe)
__global__ void k_scan_all() {
    __shared__ int sh[512];
    __shared__ int s_prefix;
    int t = threadIdx.x, b = blockIdx.x;
    int i = b * 512 + t;

    int dg = 0;
    if (i < NN) {
        dg = g_deg[i];
        g_dis[i] = rsqrtf((float)(dg + 1));
    }
    sh[t] = dg;
    __syncthreads();
    for (int o = 1; o < 512; o <<= 1) {
        int a = (t >= o) ? sh[t - o] : 0;
        __syncthreads();
        sh[t] += a;
        __syncthreads();
    }
    int incl = sh[t];

    if (t == 511) {
        g_part[b] = incl;
        __threadfence();
        atomicAdd(&g_pdone, 1);
    }
    if (t == 0) {
        volatile int* p = &g_pdone;
        while (*p < NBLK) {}
    }
    __syncthreads();

    if (t < 32) {
        int s = 0;
        for (int j = t; j < b; j += 32) s += __ldcg(&g_part[j]);
#pragma unroll
        for (int o = 16; o > 0; o >>= 1) s += __shfl_down_sync(0xFFFFFFFFu, s, o);
        if (t == 0) s_prefix = s;
    }
    __syncthreads();

    if (i < NN) g_rowptr[i] = s_prefix + incl - dg;   // exclusive
    if (i == 0) g_rowptr[NN] = NE;
}

// atomic-free CSR fill: staged-read -> 4B scatter-write (src only)
__global__ void k_fill() {
    int e = blockIdx.x * blockDim.x + threadIdx.x;
    if (e >= NE) return;
    int s   = g_srcd[e];
    int d   = g_dstd[e];
    int pos = g_pos[e];
    g_csrc[g_rowptr[d] + pos] = s;
}

// ---------------------------------------------------------------------------
// tf32 tensor-core GEMM: g_h2[row] = dis[row] * (x[row] @ W), fp16 store.
// ---------------------------------------------------------------------------
__global__ void k_gemm(const float* __restrict__ x_ext, int use_x1, int wsel) {
    const float* x = use_x1 ? g_x1 : x_ext;
    __shared__ float As[64 * 128];

    int t    = threadIdx.x;
    int base = blockIdx.x * 64;

    const float4* x4 = (const float4*)x;
    for (int i = t; i < 64 * 32; i += 256) {
        int r = i >> 5, c4 = i & 31;
        int gr = base + r;
        float4 v = make_float4(0.f, 0.f, 0.f, 0.f);
        if (gr < NN) v = x4[gr * 32 + c4];
        ((float4*)As)[r * 32 + (c4 ^ (r & 7))] = v;
    }
    __syncthreads();

    int wid  = t >> 5;
    int lane = t & 31;
    int gid  = lane >> 2;
    int tig  = lane & 3;
    int wr   = wid & 3;
    int wc   = wid >> 2;

    const uint2* wf = (const uint2*)g_wf[wsel];

    float acc[8][4];
#pragma unroll
    for (int n = 0; n < 8; n++)
#pragma unroll
        for (int j = 0; j < 4; j++) acc[n][j] = 0.f;

    int rA = wr * 16 + gid;
    int sw = gid << 2;

#pragma unroll
    for (int kt = 0; kt < 16; kt++) {
        int k0 = kt * 8;
        unsigned a0 = to_tf32(As[rA * 128 + ((k0 + tig) ^ sw)]);
        unsigned a1 = to_tf32(As[(rA + 8) * 128 + ((k0 + tig) ^ sw)]);
        unsigned a2 = to_tf32(As[rA * 128 + ((k0 + tig + 4) ^ sw)]);
        unsigned a3 = to_tf32(As[(rA + 8) * 128 + ((k0 + tig + 4) ^ sw)]);
#pragma unroll
        for (int nt = 0; nt < 8; nt++) {
            uint2 b = wf[(kt * 16 + wc * 8 + nt) * 32 + lane];
            asm volatile(
                "mma.sync.aligned.m16n8k8.row.col.f32.tf32.tf32.f32 "
                "{%0,%1,%2,%3}, {%4,%5,%6,%7}, {%8,%9}, {%0,%1,%2,%3};"
                : "+f"(acc[nt][0]), "+f"(acc[nt][1]),
                  "+f"(acc[nt][2]), "+f"(acc[nt][3])
                : "r"(a0), "r"(a1), "r"(a2), "r"(a3), "r"(b.x), "r"(b.y));
        }
    }

    int row0 = base + wr * 16 + gid;
    float dn0 = (row0 < NN)     ? g_dis[row0]     : 0.f;
    float dn8 = (row0 + 8 < NN) ? g_dis[row0 + 8] : 0.f;
#pragma unroll
    for (int nt = 0; nt < 8; nt++) {
        int c2i = wc * 32 + nt * 4 + tig;
        if (row0 < NN)
            g_h2[row0 * 64 + c2i] =
                __floats2half2_rn(dn0 * acc[nt][0], dn0 * acc[nt][1]);
        if (row0 + 8 < NN)
            g_h2[(row0 + 8) * 64 + c2i] =
                __floats2half2_rn(dn8 * acc[nt][2], dn8 * acc[nt][3]);
    }
}

__device__ __forceinline__ void agg_add(float4& a, uint2 u) {
    float2 lo = __half22float2(*(const __half2*)&u.x);
    float2 hi = __half22float2(*(const __half2*)&u.y);
    a.x += lo.x;
    a.y += lo.y;
    a.z += hi.x;
    a.w += hi.y;
}

// Aggregation: warp per node; lane = 4 cols. Edge indices software-pipelined
// one quad ahead so the csrc-load latency overlaps the h-row gathers.
// out[d] = dis[d] * ( sum_e h'[src_e] + h'[d] ) + bias,  h' = dis*h (fp16)
__global__ void k_agg(const float* __restrict__ bias, float* __restrict__ out_ext,
                      int layer) {
    int node = blockIdx.x * (blockDim.x >> 5) + (threadIdx.x >> 5);
    if (node >= NN) return;
    int lane = threadIdx.x & 31;

    int beg = g_rowptr[node];
    int end = g_rowptr[node + 1];

    const uint2* h8 = (const uint2*)g_h2;
    float4 A0 = make_float4(0.f, 0.f, 0.f, 0.f);
    float4 A1 = make_float4(0.f, 0.f, 0.f, 0.f);
    float4 A2 = make_float4(0.f, 0.f, 0.f, 0.f);
    float4 A3 = make_float4(0.f, 0.f, 0.f, 0.f);

    int e = beg;
    int s0 = 0, s1 = 0, s2 = 0, s3 = 0;
    bool have = (e + 4 <= end);
    if (have) {
        s0 = g_csrc[e];
        s1 = g_csrc[e + 1];
        s2 = g_csrc[e + 2];
        s3 = g_csrc[e + 3];
    }
    while (have) {
        int  ne = e + 4;
        bool nh = (ne + 4 <= end);
        int n0 = 0, n1 = 0, n2 = 0, n3 = 0;
        if (nh) {                     // prefetch next quad's indices
            n0 = g_csrc[ne];
            n1 = g_csrc[ne + 1];
            n2 = g_csrc[ne + 2];
            n3 = g_csrc[ne + 3];
        }
        uint2 u0 = __ldcg(&h8[s0 * 32 + lane]);
        uint2 u1 = __ldcg(&h8[s1 * 32 + lane]);
        uint2 u2 = __ldcg(&h8[s2 * 32 + lane]);
        uint2 u3 = __ldcg(&h8[s3 * 32 + lane]);
        agg_add(A0, u0);
        agg_add(A1, u1);
        agg_add(A2, u2);
        agg_add(A3, u3);
        e = ne;
        s0 = n0; s1 = n1; s2 = n2; s3 = n3;
        have = nh;
    }
    for (; e < end; e++) {
        int s = g_csrc[e];
        uint2 u = __ldcg(&h8[s * 32 + lane]);
        agg_add(A0, u);
    }

    // self term (h' already dis-scaled)
    uint2 uh = h8[node * 32 + lane];
    agg_add(A0, uh);

    A0.x += A1.x + A2.x + A3.x;
    A0.y += A1.y + A2.y + A3.y;
    A0.z += A1.z + A2.z + A3.z;
    A0.w += A1.w + A2.w + A3.w;

    float dn = g_dis[node];
    float4 b = ((const float4*)bias)[lane];

    float4 r;
    r.x = dn * A0.x + b.x;
    r.y = dn * A0.y + b.y;
    r.z = dn * A0.z + b.z;
    r.w = dn * A0.w + b.w;

    if (layer == 0) {
        r.x = fmaxf(r.x, 0.f);
        r.y = fmaxf(r.y, 0.f);
        r.z = fmaxf(r.z, 0.f);
        r.w = fmaxf(r.w, 0.f);
        ((float4*)g_x1)[node * 32 + lane] = r;
    } else {
        ((float4*)out_ext)[node * 32 + lane] = r;
    }
}

extern "C" void kernel_launch(void* const* d_in, const int* in_sizes, int n_in,
                              void* d_out, int out_size) {
    const void*  ei  = d_in[0];
    const float* emb = (const float*)d_in[1];
    const float* W1  = (const float*)d_in[2];
    const float* b1  = (const float*)d_in[3];
    const float* W2  = (const float*)d_in[4];
    const float* b2  = (const float*)d_in[5];
    float* out = (float*)d_out;

    (void)in_sizes; (void)n_in; (void)out_size;

    k_init<<<196, 256>>>((const int*)ei, W1, W2);   // zero+detect+wfrag
    k_prep<<<(NE + 255) / 256, 256>>>(ei);          // decode+count+slot (1 atomic pass)
    k_scan_all<<<NBLK, 512>>>();                    // dis + exclusive scan
    k_fill<<<(NE + 255) / 256, 256>>>();            // atomic-free 4B scatter

    k_gemm<<<GBLK, 256>>>(emb, 0, 0);               // layer-1 GEMM (tf32 -> dis*h fp16)
    k_agg<<<(NN + 7) / 8, 256>>>(b1, out, 0);       // -> g_x1 (relu, fp32)

    k_gemm<<<GBLK, 256>>>(nullptr, 1, 1);           // layer-2 GEMM
    k_agg<<<(NN + 7) / 8, 256>>>(b2, out, 1);       // -> d_out
}

// round 16
// speedup vs baseline: 1.2454x; 1.0148x over previous
#include <cuda_runtime.h>
#include <cuda_fp16.h>
#include <cstdint>

#define NN 50000
#define NE 800000
#define D  128
#define NBLK 98                  // ceil(50000/512) scan blocks
#define GBLK 782                 // ceil(50000/64) gemm blocks
#define FBLK 3125                // ceil(NE/256) fill blocks

// ---- scratch (no allocations allowed) ----
__device__ int      g_deg[NN];
__device__ int      g_rowptr[NN + 1];
__device__ int      g_srcd[NE];      // staged src
__device__ int      g_dstd[NE];      // staged dst
__device__ int      g_pos[NE];       // staged within-dst slot
__device__ int      g_csrc[NE];      // CSR: src per slot (dis folded into h)
__device__ float    g_dis[NN];
__device__ __half2  g_h2[NN * 64];   // GEMM output, fp16, pre-scaled by dis[row]
__device__ __half2  g_x1h[NN * 64];  // layer-1 activation (fp16)
__device__ int      g_part[NBLK];
__device__ int      g_pdone;
__device__ int      g_is64;
__device__ unsigned g_wf[2][16384];  // fragment-ordered tf32 weights

__device__ __forceinline__ unsigned to_tf32(float f) {
    unsigned r;
    asm("cvt.rna.tf32.f32 %0, %1;" : "=r"(r) : "f"(f));
    return r;
}

// init: zero deg, reset scan flag, dtype-detect, build fragment-ordered tf32 W1/W2.
__global__ void k_init(const int* __restrict__ ei32,
                       const float* __restrict__ W1,
                       const float* __restrict__ W2) {
    int i = blockIdx.x * blockDim.x + threadIdx.x;
    if (i < NN) g_deg[i] = 0;
    if (i == 0) g_pdone = 0;
    if (i < 32768) {
        int l  = (i >= 16384) ? 1 : 0;
        int j  = i & 16383;
        int r  = j & 1;
        int ln = (j >> 1) & 31;
        int nt = (j >> 6) & 15;
        int kt = j >> 10;
        int k  = kt * 8 + (ln & 3) + r * 4;
        int n  = nt * 8 + (ln >> 2);
        const float* W = l ? W2 : W1;
        g_wf[l][j] = to_tf32(W[k * 128 + n]);
    }
    if (blockIdx.x == 0 && threadIdx.x < 32) {
        int lane = threadIdx.x;
        int acc = 0;
        for (int jj = 0; jj < 8; jj++) acc |= ei32[1 + 2 * (lane + 32 * jj)];
        unsigned b = __ballot_sync(0xFFFFFFFFu, acc != 0);
        if (lane == 0) g_is64 = (b == 0) ? 1 : 0;
    }
}

// decode + degree-count + slot assignment (single atomic pass over edges)
__global__ void k_prep(const void* __restrict__ eiv) {
    int e = blockIdx.x * blockDim.x + threadIdx.x;
    if (e >= NE) return;
    int s, d;
    if (g_is64) {
        const long long* ei = (const long long*)eiv;
        s = (int)ei[e];
        d = (int)ei[NE + e];
    } else {
        const int* ei = (const int*)eiv;
        s = ei[e];
        d = ei[NE + e];
    }
    if ((unsigned)s >= NN) s = 0;
    if ((unsigned)d >= NN) d = 0;
    int pos = atomicAdd(&g_deg[d], 1);
    g_srcd[e] = s;
    g_dstd[e] = d;
    g_pos[e]  = pos;
}

// fused dis + exclusive scan (98 blocks <= 148 SMs -> co-resident, spin safe)
__global__ void k_scan_all() {
    __shared__ int sh[512];
    __shared__ int s_prefix;
    int t = threadIdx.x, b = blockIdx.x;
    int i = b * 512 + t;

    int dg = 0;
    if (i < NN) {
        dg = g_deg[i];
        g_dis[i] = rsqrtf((float)(dg + 1));
    }
    sh[t] = dg;
    __syncthreads();
    for (int o = 1; o < 512; o <<= 1) {
        int a = (t >= o) ? sh[t - o] : 0;
        __syncthreads();
        sh[t] += a;
        __syncthreads();
    }
    int incl = sh[t];

    if (t == 511) {
        g_part[b] = incl;
        __threadfence();
        atomicAdd(&g_pdone, 1);
    }
    if (t == 0) {
        volatile int* p = &g_pdone;
        while (*p < NBLK) {}
    }
    __syncthreads();

    if (t < 32) {
        int s = 0;
        for (int j = t; j < b; j += 32) s += __ldcg(&g_part[j]);
#pragma unroll
        for (int o = 16; o > 0; o >>= 1) s += __shfl_down_sync(0xFFFFFFFFu, s, o);
        if (t == 0) s_prefix = s;
    }
    __syncthreads();

    if (i < NN) g_rowptr[i] = s_prefix + incl - dg;   // exclusive
    if (i == 0) g_rowptr[NN] = NE;
}

// ---------------------------------------------------------------------------
// GEMM core: g_h2[row] = dis[row] * (x[row] @ W), fp16 store, tf32 mma.
// x source: fp32 (emb) when x16 == nullptr, else fp16 (g_x1h).
// ---------------------------------------------------------------------------
__device__ __forceinline__ void gemm_core(const float* __restrict__ x32,
                                          const uint2* __restrict__ x16,
                                          int wsel, int base, float* As) {
    int t = threadIdx.x;

    if (x16) {
        for (int i = t; i < 64 * 32; i += 256) {
            int r = i >> 5, c4 = i & 31;
            int gr = base + r;
            float4 v = make_float4(0.f, 0.f, 0.f, 0.f);
            if (gr < NN) {
                uint2 u = x16[gr * 32 + c4];
                float2 lo = __half22float2(*(const __half2*)&u.x);
                float2 hi = __half22float2(*(const __half2*)&u.y);
                v = make_float4(lo.x, lo.y, hi.x, hi.y);
            }
            ((float4*)As)[r * 32 + (c4 ^ (r & 7))] = v;
        }
    } else {
        const float4* x4 = (const float4*)x32;
        for (int i = t; i < 64 * 32; i += 256) {
            int r = i >> 5, c4 = i & 31;
            int gr = base + r;
            float4 v = make_float4(0.f, 0.f, 0.f, 0.f);
            if (gr < NN) v = x4[gr * 32 + c4];
            ((float4*)As)[r * 32 + (c4 ^ (r & 7))] = v;
        }
    }
    __syncthreads();

    int wid  = t >> 5;
    int lane = t & 31;
    int gid  = lane >> 2;
    int tig  = lane & 3;
    int wr   = wid & 3;
    int wc   = wid >> 2;

    const uint2* wf = (const uint2*)g_wf[wsel];

    float acc[8][4];
#pragma unroll
    for (int n = 0; n < 8; n++)
#pragma unroll
        for (int j = 0; j < 4; j++) acc[n][j] = 0.f;

    int rA = wr * 16 + gid;
    int sw = gid << 2;

#pragma unroll
    for (int kt = 0; kt < 16; kt++) {
        int k0 = kt * 8;
        unsigned a0 = to_tf32(As[rA * 128 + ((k0 + tig) ^ sw)]);
        unsigned a1 = to_tf32(As[(rA + 8) * 128 + ((k0 + tig) ^ sw)]);
        unsigned a2 = to_tf32(As[rA * 128 + ((k0 + tig + 4) ^ sw)]);
        unsigned a3 = to_tf32(As[(rA + 8) * 128 + ((k0 + tig + 4) ^ sw)]);
#pragma unroll
        for (int nt = 0; nt < 8; nt++) {
            uint2 b = wf[(kt * 16 + wc * 8 + nt) * 32 + lane];
            asm volatile(
                "mma.sync.aligned.m16n8k8.row.col.f32.tf32.tf32.f32 "
                "{%0,%1,%2,%3}, {%4,%5,%6,%7}, {%8,%9}, {%0,%1,%2,%3};"
                : "+f"(acc[nt][0]), "+f"(acc[nt][1]),
                  "+f"(acc[nt][2]), "+f"(acc[nt][3])
                : "r"(a0), "r"(a1), "r"(a2), "r"(a3), "r"(b.x), "r"(b.y));
        }
    }

    int row0 = base + wr * 16 + gid;
    float dn0 = (row0 < NN)     ? g_dis[row0]     : 0.f;
    float dn8 = (row0 + 8 < NN) ? g_dis[row0 + 8] : 0.f;
#pragma unroll
    for (int nt = 0; nt < 8; nt++) {
        int c2i = wc * 32 + nt * 4 + tig;
        if (row0 < NN)
            g_h2[row0 * 64 + c2i] =
                __floats2half2_rn(dn0 * acc[nt][0], dn0 * acc[nt][1]);
        if (row0 + 8 < NN)
            g_h2[(row0 + 8) * 64 + c2i] =
                __floats2half2_rn(dn8 * acc[nt][2], dn8 * acc[nt][3]);
    }
}

// Fused: blocks [0,GBLK) = layer-1 GEMM (needs g_dis); [GBLK,GBLK+FBLK) = CSR fill.
// Both depend only on scan_all -> safe siblings, disjoint pipes.
__global__ void k_gemm1_fill(const float* __restrict__ emb) {
    __shared__ float As[64 * 128];
    int b = blockIdx.x;
    if (b < GBLK) {
        gemm_core(emb, nullptr, 0, b * 64, As);
        return;
    }
    int e = (b - GBLK) * 256 + threadIdx.x;
    if (e >= NE) return;
    int s   = g_srcd[e];
    int d   = g_dstd[e];
    int pos = g_pos[e];
    g_csrc[g_rowptr[d] + pos] = s;
}

// layer-2 GEMM (reads fp16 x1)
__global__ void k_gemm2() {
    __shared__ float As[64 * 128];
    gemm_core(nullptr, (const uint2*)g_x1h, 1, blockIdx.x * 64, As);
}

__device__ __forceinline__ void agg_add(float4& a, uint2 u) {
    float2 lo = __half22float2(*(const __half2*)&u.x);
    float2 hi = __half22float2(*(const __half2*)&u.y);
    a.x += lo.x;
    a.y += lo.y;
    a.z += hi.x;
    a.w += hi.y;
}

// Aggregation: warp per node; lane = 4 cols; indices pipelined one quad ahead.
// out[d] = dis[d] * ( sum_e h'[src_e] + h'[d] ) + bias,  h' = dis*h (fp16)
__global__ void k_agg(const float* __restrict__ bias, float* __restrict__ out_ext,
                      int layer) {
    int node = blockIdx.x * (blockDim.x >> 5) + (threadIdx.x >> 5);
    if (node >= NN) return;
    int lane = threadIdx.x & 31;

    int beg = g_rowptr[node];
    int end = g_rowptr[node + 1];

    const uint2* h8 = (const uint2*)g_h2;
    float4 A0 = make_float4(0.f, 0.f, 0.f, 0.f);
    float4 A1 = make_float4(0.f, 0.f, 0.f, 0.f);
    float4 A2 = make_float4(0.f, 0.f, 0.f, 0.f);
    float4 A3 = make_float4(0.f, 0.f, 0.f, 0.f);

    int e = beg;
    int s0 = 0, s1 = 0, s2 = 0, s3 = 0;
    bool have = (e + 4 <= end);
    if (have) {
        s0 = g_csrc[e];
        s1 = g_csrc[e + 1];
        s2 = g_csrc[e + 2];
        s3 = g_csrc[e + 3];
    }
    while (have) {
        int  ne = e + 4;
        bool nh = (ne + 4 <= end);
        int n0 = 0, n1 = 0, n2 = 0, n3 = 0;
        if (nh) {
            n0 = g_csrc[ne];
            n1 = g_csrc[ne + 1];
            n2 = g_csrc[ne + 2];
            n3 = g_csrc[ne + 3];
        }
        uint2 u0 = __ldcg(&h8[s0 * 32 + lane]);
        uint2 u1 = __ldcg(&h8[s1 * 32 + lane]);
        uint2 u2 = __ldcg(&h8[s2 * 32 + lane]);
        uint2 u3 = __ldcg(&h8[s3 * 32 + lane]);
        agg_add(A0, u0);
        agg_add(A1, u1);
        agg_add(A2, u2);
        agg_add(A3, u3);
        e = ne;
        s0 = n0; s1 = n1; s2 = n2; s3 = n3;
        have = nh;
    }
    for (; e < end; e++) {
        int s = g_csrc[e];
        uint2 u = __ldcg(&h8[s * 32 + lane]);
        agg_add(A0, u);
    }

    // self term (h' already dis-scaled)
    uint2 uh = h8[node * 32 + lane];
    agg_add(A0, uh);

    A0.x += A1.x + A2.x + A3.x;
    A0.y += A1.y + A2.y + A3.y;
    A0.z += A1.z + A2.z + A3.z;
    A0.w += A1.w + A2.w + A3.w;

    float dn = g_dis[node];
    float4 b = ((const float4*)bias)[lane];

    float4 r;
    r.x = dn * A0.x + b.x;
    r.y = dn * A0.y + b.y;
    r.z = dn * A0.z + b.z;
    r.w = dn * A0.w + b.w;

    if (layer == 0) {
        r.x = fmaxf(r.x, 0.f);
        r.y = fmaxf(r.y, 0.f);
        r.z = fmaxf(r.z, 0.f);
        r.w = fmaxf(r.w, 0.f);
        uint2 w;
        *(__half2*)&w.x = __floats2half2_rn(r.x, r.y);
        *(__half2*)&w.y = __floats2half2_rn(r.z, r.w);
        ((uint2*)g_x1h)[node * 32 + lane] = w;
    } else {
        ((float4*)out_ext)[node * 32 + lane] = r;
    }
}

extern "C" void kernel_launch(void* const* d_in, const int* in_sizes, int n_in,
                              void* d_out, int out_size) {
    const void*  ei  = d_in[0];
    const float* emb = (const float*)d_in[1];
    const float* W1  = (const float*)d_in[2];
    const float* b1  = (const float*)d_in[3];
    const float* W2  = (const float*)d_in[4];
    const float* b2  = (const float*)d_in[5];
    float* out = (float*)d_out;

    (void)in_sizes; (void)n_in; (void)out_size;

    k_init<<<196, 256>>>((const int*)ei, W1, W2);   // zero+detect+wfrag
    k_prep<<<(NE + 255) / 256, 256>>>(ei);          // decode+count+slot (1 atomic pass)
    k_scan_all<<<NBLK, 512>>>();                    // dis + exclusive scan
    k_gemm1_fill<<<GBLK + FBLK, 256>>>(emb);        // GEMM1 ∥ CSR fill (siblings)
    k_agg<<<(NN + 7) / 8, 256>>>(b1, out, 0);       // -> g_x1h (relu, fp16)
    k_gemm2<<<GBLK, 256>>>();                       // layer-2 GEMM (fp16 A)
    k_agg<<<(NN + 7) / 8, 256>>>(b2, out, 1);       // -> d_out
}